// round 7
// baseline (speedup 1.0000x reference)
#include <cuda_runtime.h>
#include <cuda_fp16.h>
#include <stdint.h>

// out[num_rows, 128] = segment_sum(W[cols]*vals, rows) + b
//
// R6: two launches only.
//   k1 scatter_convert: 4-wide vectorized metadata reads -> per-row slots;
//      W fp32 -> fp16 conversion rides along on the first 262144 threads.
//   k2 row_gather: warp per row, half-warp split (R5), fp32 accumulation,
//      single float4 store per lane. Self-resets g_cnt / g_ovf_n / g_done
//      so no zero kernel is needed (device globals start zeroed; the reset
//      restores the invariant before every graph replay).

static constexpr int UNITS    = 128;
static constexpr int WCOLS    = 8192;
static constexpr int SLOTS    = 48;
static constexpr int MAX_ROWS = 1 << 17;
static constexpr int OVF_CAP  = 65536;

__device__ __align__(16) __half g_Wh[WCOLS * UNITS];  // 2 MB fp16 W
__device__ int    g_cnt[MAX_ROWS];                    // zero-init, self-reset
__device__ float2 g_slot[(size_t)MAX_ROWS * SLOTS];   // (val, bitcast(col))
__device__ float4 g_ovf[OVF_CAP];                     // (val, col, row, -)
__device__ int    g_ovf_n;                            // zero-init, self-reset
__device__ int    g_done;                             // zero-init, self-reset

// ---- k1: scatter nonzeros into per-row slots (4-wide) + convert W ----
__global__ void scatter_convert_kernel(const float* __restrict__ vals,
                                       const int* __restrict__ rows,
                                       const int* __restrict__ cols,
                                       const float* __restrict__ W,
                                       int nnz, int n4) {
    int t = blockIdx.x * blockDim.x + threadIdx.x;

    if (t < n4) {  // W conversion (262144 float4s)
        float4 f = __ldg(reinterpret_cast<const float4*>(W) + t);
        __half2 h0 = __floats2half2_rn(f.x, f.y);
        __half2 h1 = __floats2half2_rn(f.z, f.w);
        uint2 u;
        u.x = *reinterpret_cast<uint32_t*>(&h0);
        u.y = *reinterpret_cast<uint32_t*>(&h1);
        reinterpret_cast<uint2*>(g_Wh)[t] = u;
    }

    int i0 = t * 4;
    if (i0 >= nnz) return;

    if (i0 + 4 <= nnz) {
        float4 v4 = __ldg(reinterpret_cast<const float4*>(vals + i0));
        int4   r4 = __ldg(reinterpret_cast<const int4*>(rows + i0));
        int4   c4 = __ldg(reinterpret_cast<const int4*>(cols + i0));
        float vv[4] = {v4.x, v4.y, v4.z, v4.w};
        int   rr[4] = {r4.x, r4.y, r4.z, r4.w};
        int   cc[4] = {c4.x, c4.y, c4.z, c4.w};
        #pragma unroll
        for (int q = 0; q < 4; ++q) {
            int pos = atomicAdd(&g_cnt[rr[q]], 1);
            if (pos < SLOTS) {
                g_slot[(size_t)rr[q] * SLOTS + pos] =
                    make_float2(vv[q], __int_as_float(cc[q]));
            } else {
                int op = atomicAdd(&g_ovf_n, 1);
                if (op < OVF_CAP)
                    g_ovf[op] = make_float4(vv[q], __int_as_float(cc[q]),
                                            __int_as_float(rr[q]), 0.f);
            }
        }
    } else {
        for (int i = i0; i < nnz; ++i) {
            int   r = rows[i];
            float v = vals[i];
            int   c = cols[i];
            int pos = atomicAdd(&g_cnt[r], 1);
            if (pos < SLOTS) {
                g_slot[(size_t)r * SLOTS + pos] = make_float2(v, __int_as_float(c));
            } else {
                int op = atomicAdd(&g_ovf_n, 1);
                if (op < OVF_CAP)
                    g_ovf[op] = make_float4(v, __int_as_float(c),
                                            __int_as_float(r), 0.f);
            }
        }
    }
}

// ---- k2: warp per row; half-warp split; self-resetting counters ----
__global__ void __launch_bounds__(256) row_gather_kernel(
        const float* __restrict__ b,
        float* __restrict__ out,
        int num_rows) {
    int warp = (blockIdx.x * blockDim.x + threadIdx.x) >> 5;
    int lane = threadIdx.x & 31;
    if (warp >= num_rows) return;

    int hi  = lane >> 4;        // which nonzero of the pair this lane serves
    int sub = lane & 15;        // covers units [8*sub, 8*sub+8)

    int cnt_raw = g_cnt[warp];
    int cnt = cnt_raw > SLOTS ? SLOTS : cnt_raw;
    int ovn = g_ovf_n;          // read BEFORE the done-arrive below

    const char* Wl = reinterpret_cast<const char*>(g_Wh) + sub * 16;
    const float2* slots = g_slot + (size_t)warp * SLOTS;

    float4 accA = make_float4(0.f, 0.f, 0.f, 0.f);
    float4 accB = make_float4(0.f, 0.f, 0.f, 0.f);

    for (int k = 0; k < cnt; k += 32) {
        int m = cnt - k;
        if (m > 32) m = 32;
        float v = 0.f;
        int   c = 0;
        if (lane < m) {
            float2 p = __ldg(slots + k + lane);
            v = p.x;
            c = __float_as_int(p.y);
        }

        int iters = (m + 1) >> 1;
        #pragma unroll 4
        for (int p = 0; p < iters; ++p) {
            int j  = 2 * p + hi;
            float vj = __shfl_sync(0xffffffffu, v, j);    // 0 if j >= m
            int   cj = __shfl_sync(0xffffffffu, c, j);

            uint4 u = __ldg(reinterpret_cast<const uint4*>(
                          Wl + ((size_t)(uint32_t)cj << 8)));
            float2 f0 = __half22float2(*reinterpret_cast<__half2*>(&u.x));
            float2 f1 = __half22float2(*reinterpret_cast<__half2*>(&u.y));
            float2 f2 = __half22float2(*reinterpret_cast<__half2*>(&u.z));
            float2 f3 = __half22float2(*reinterpret_cast<__half2*>(&u.w));
            accA.x = fmaf(f0.x, vj, accA.x);
            accA.y = fmaf(f0.y, vj, accA.y);
            accA.z = fmaf(f1.x, vj, accA.z);
            accA.w = fmaf(f1.y, vj, accA.w);
            accB.x = fmaf(f2.x, vj, accB.x);
            accB.y = fmaf(f2.y, vj, accB.y);
            accB.z = fmaf(f3.x, vj, accB.z);
            accB.w = fmaf(f3.y, vj, accB.w);
        }
    }

    // Combine even/odd half-warp partials.
    accA.x += __shfl_xor_sync(0xffffffffu, accA.x, 16);
    accA.y += __shfl_xor_sync(0xffffffffu, accA.y, 16);
    accA.z += __shfl_xor_sync(0xffffffffu, accA.z, 16);
    accA.w += __shfl_xor_sync(0xffffffffu, accA.w, 16);
    accB.x += __shfl_xor_sync(0xffffffffu, accB.x, 16);
    accB.y += __shfl_xor_sync(0xffffffffu, accB.y, 16);
    accB.z += __shfl_xor_sync(0xffffffffu, accB.z, 16);
    accB.w += __shfl_xor_sync(0xffffffffu, accB.w, 16);

    int ubase = sub * 8 + hi * 4;
    float4 r = hi ? accB : accA;

    // Inline overflow fixup (expected empty).
    if (ovn > 0) {
        if (ovn > OVF_CAP) ovn = OVF_CAP;
        for (int e = 0; e < ovn; ++e) {
            float4 ent = g_ovf[e];
            if (__float_as_int(ent.z) == warp) {
                float ve = ent.x;
                size_t ce = (size_t)(uint32_t)__float_as_int(ent.y);
                uint2 u = __ldg(reinterpret_cast<const uint2*>(
                              g_Wh + ce * UNITS + ubase));
                float2 e0 = __half22float2(*reinterpret_cast<__half2*>(&u.x));
                float2 e1 = __half22float2(*reinterpret_cast<__half2*>(&u.y));
                r.x = fmaf(e0.x, ve, r.x);
                r.y = fmaf(e0.y, ve, r.y);
                r.z = fmaf(e1.x, ve, r.z);
                r.w = fmaf(e1.y, ve, r.w);
            }
        }
    }

    float4 bias = __ldg(reinterpret_cast<const float4*>(b) + (ubase >> 2));
    r.x += bias.x; r.y += bias.y; r.z += bias.z; r.w += bias.w;
    *reinterpret_cast<float4*>(out + (size_t)warp * UNITS + ubase) = r;

    // ---- self-reset for the next invocation / graph replay ----
    if (lane == 0) {
        g_cnt[warp] = 0;                       // own-row reset (safe: only this
                                               // warp reads g_cnt[warp])
        __threadfence();
        int d = atomicAdd(&g_done, 1);
        if (d == num_rows - 1) {               // last warp overall
            g_ovf_n = 0;
            g_done  = 0;
            __threadfence();
        }
    }
}

extern "C" void kernel_launch(void* const* d_in, const int* in_sizes, int n_in,
                              void* d_out, int out_size) {
    const float* vals = (const float*)d_in[0];
    const int*   rows = (const int*)d_in[1];
    const int*   cols = (const int*)d_in[2];
    const float* W    = (const float*)d_in[3];
    const float* b    = (const float*)d_in[4];
    float* out = (float*)d_out;

    int nnz = in_sizes[0];
    int num_rows = out_size / UNITS;

    const int T = 256;
    int n4 = WCOLS * UNITS / 4;             // 262144 float4s of W
    int nq = (nnz + 3) / 4;                 // threads for 4-wide scatter
    int work = nq > n4 ? nq : n4;

    scatter_convert_kernel<<<(work + T - 1) / T, T>>>(vals, rows, cols, W, nnz, n4);
    int gblocks = (int)(((long)num_rows * 32 + T - 1) / T);
    row_gather_kernel<<<gblocks, T>>>(b, out, num_rows);
}

// round 8
// speedup vs baseline: 1.3777x; 1.3777x over previous
#include <cuda_runtime.h>
#include <cuda_fp16.h>
#include <stdint.h>

// out[num_rows, 128] = segment_sum(W[cols]*vals, rows) + b
//
// R7: revert R6's self-reset regression (single-address g_done atomic +
// threadfence serialized the hot kernel). Structure = R5 (86.8us known-good):
//   k0 zero counters (3.8us, cheap)
//   k1 scatter+convert: NOW 2 nnz/thread, two independent ATOMG chains
//   k2 row_gather: R5 half-warp split loop, unroll raised 4 -> 8 for MLP

static constexpr int UNITS    = 128;
static constexpr int WCOLS    = 8192;
static constexpr int SLOTS    = 48;
static constexpr int MAX_ROWS = 1 << 17;
static constexpr int OVF_CAP  = 65536;

__device__ __align__(16) __half g_Wh[WCOLS * UNITS];  // 2 MB fp16 W
__device__ int    g_cnt[MAX_ROWS];
__device__ float2 g_slot[(size_t)MAX_ROWS * SLOTS];   // (val, bitcast(col))
__device__ float4 g_ovf[OVF_CAP];                     // (val, col, row, -)
__device__ int    g_ovf_n;

// ---- k0: zero per-row counters + overflow counter ----
__global__ void zero_kernel(int num_rows) {
    int i = blockIdx.x * blockDim.x + threadIdx.x;
    if (i < num_rows) g_cnt[i] = 0;
    if (i == 0) g_ovf_n = 0;
}

__device__ __forceinline__ void bin_one(float v, int r, int c) {
    int pos = atomicAdd(&g_cnt[r], 1);
    if (pos < SLOTS) {
        g_slot[(size_t)r * SLOTS + pos] = make_float2(v, __int_as_float(c));
    } else {
        int op = atomicAdd(&g_ovf_n, 1);
        if (op < OVF_CAP)
            g_ovf[op] = make_float4(v, __int_as_float(c), __int_as_float(r), 0.f);
    }
}

// ---- k1: scatter nonzeros into per-row slots (2/thread) + convert W ----
__global__ void scatter_convert_kernel(const float* __restrict__ vals,
                                       const int* __restrict__ rows,
                                       const int* __restrict__ cols,
                                       const float* __restrict__ W,
                                       int nnz, int n4) {
    int t = blockIdx.x * blockDim.x + threadIdx.x;

    if (t < n4) {  // W conversion rides along on the first 262144 threads
        float4 f = __ldg(reinterpret_cast<const float4*>(W) + t);
        __half2 h0 = __floats2half2_rn(f.x, f.y);
        __half2 h1 = __floats2half2_rn(f.z, f.w);
        uint2 u;
        u.x = *reinterpret_cast<uint32_t*>(&h0);
        u.y = *reinterpret_cast<uint32_t*>(&h1);
        reinterpret_cast<uint2*>(g_Wh)[t] = u;
    }

    int i0 = t * 2;
    if (i0 >= nnz) return;

    if (i0 + 2 <= nnz) {
        float2 v2 = __ldg(reinterpret_cast<const float2*>(vals + i0));
        int2   r2 = __ldg(reinterpret_cast<const int2*>(rows + i0));
        int2   c2 = __ldg(reinterpret_cast<const int2*>(cols + i0));
        // Two independent atomic->store chains (ILP over 318-cyc ATOMG).
        int pos0 = atomicAdd(&g_cnt[r2.x], 1);
        int pos1 = atomicAdd(&g_cnt[r2.y], 1);
        if (pos0 < SLOTS) {
            g_slot[(size_t)r2.x * SLOTS + pos0] = make_float2(v2.x, __int_as_float(c2.x));
        } else {
            int op = atomicAdd(&g_ovf_n, 1);
            if (op < OVF_CAP)
                g_ovf[op] = make_float4(v2.x, __int_as_float(c2.x), __int_as_float(r2.x), 0.f);
        }
        if (pos1 < SLOTS) {
            g_slot[(size_t)r2.y * SLOTS + pos1] = make_float2(v2.y, __int_as_float(c2.y));
        } else {
            int op = atomicAdd(&g_ovf_n, 1);
            if (op < OVF_CAP)
                g_ovf[op] = make_float4(v2.y, __int_as_float(c2.y), __int_as_float(r2.y), 0.f);
        }
    } else {
        bin_one(vals[i0], rows[i0], cols[i0]);
    }
}

// ---- k2: warp per row; half-warp split: lanes 0-15 even nnz, 16-31 odd ----
__global__ void __launch_bounds__(256) row_gather_kernel(
        const float* __restrict__ b,
        float* __restrict__ out,
        int num_rows) {
    int warp = (blockIdx.x * blockDim.x + threadIdx.x) >> 5;
    int lane = threadIdx.x & 31;
    if (warp >= num_rows) return;

    int hi  = lane >> 4;        // which nonzero of the pair this lane serves
    int sub = lane & 15;        // covers units [8*sub, 8*sub+8)

    int cnt = g_cnt[warp];
    if (cnt > SLOTS) cnt = SLOTS;

    const char* Wl = reinterpret_cast<const char*>(g_Wh) + sub * 16;
    const float2* slots = g_slot + (size_t)warp * SLOTS;

    float4 accA = make_float4(0.f, 0.f, 0.f, 0.f);  // units [8s, 8s+4)
    float4 accB = make_float4(0.f, 0.f, 0.f, 0.f);  // units [8s+4, 8s+8)

    for (int k = 0; k < cnt; k += 32) {
        int m = cnt - k;
        if (m > 32) m = 32;
        float v = 0.f;
        int   c = 0;
        if (lane < m) {
            float2 p = __ldg(slots + k + lane);
            v = p.x;
            c = __float_as_int(p.y);
        }

        int iters = (m + 1) >> 1;
        #pragma unroll 8
        for (int p = 0; p < iters; ++p) {
            int j  = 2 * p + hi;
            float vj = __shfl_sync(0xffffffffu, v, j);    // 0 if j >= m
            int   cj = __shfl_sync(0xffffffffu, c, j);

            uint4 u = __ldg(reinterpret_cast<const uint4*>(
                          Wl + ((size_t)(uint32_t)cj << 8)));
            float2 f0 = __half22float2(*reinterpret_cast<__half2*>(&u.x));
            float2 f1 = __half22float2(*reinterpret_cast<__half2*>(&u.y));
            float2 f2 = __half22float2(*reinterpret_cast<__half2*>(&u.z));
            float2 f3 = __half22float2(*reinterpret_cast<__half2*>(&u.w));
            accA.x = fmaf(f0.x, vj, accA.x);
            accA.y = fmaf(f0.y, vj, accA.y);
            accA.z = fmaf(f1.x, vj, accA.z);
            accA.w = fmaf(f1.y, vj, accA.w);
            accB.x = fmaf(f2.x, vj, accB.x);
            accB.y = fmaf(f2.y, vj, accB.y);
            accB.z = fmaf(f3.x, vj, accB.z);
            accB.w = fmaf(f3.y, vj, accB.w);
        }
    }

    // Combine even/odd half-warp partials.
    accA.x += __shfl_xor_sync(0xffffffffu, accA.x, 16);
    accA.y += __shfl_xor_sync(0xffffffffu, accA.y, 16);
    accA.z += __shfl_xor_sync(0xffffffffu, accA.z, 16);
    accA.w += __shfl_xor_sync(0xffffffffu, accA.w, 16);
    accB.x += __shfl_xor_sync(0xffffffffu, accB.x, 16);
    accB.y += __shfl_xor_sync(0xffffffffu, accB.y, 16);
    accB.z += __shfl_xor_sync(0xffffffffu, accB.z, 16);
    accB.w += __shfl_xor_sync(0xffffffffu, accB.w, 16);

    int ubase = sub * 8 + hi * 4;
    float4 r = hi ? accB : accA;

    // Inline overflow fixup (expected empty).
    int ovn = g_ovf_n;
    if (ovn > 0) {
        if (ovn > OVF_CAP) ovn = OVF_CAP;
        for (int e = 0; e < ovn; ++e) {
            float4 ent = g_ovf[e];
            if (__float_as_int(ent.z) == warp) {
                float ve = ent.x;
                size_t ce = (size_t)(uint32_t)__float_as_int(ent.y);
                uint2 u = __ldg(reinterpret_cast<const uint2*>(
                              g_Wh + ce * UNITS + ubase));
                float2 e0 = __half22float2(*reinterpret_cast<__half2*>(&u.x));
                float2 e1 = __half22float2(*reinterpret_cast<__half2*>(&u.y));
                r.x = fmaf(e0.x, ve, r.x);
                r.y = fmaf(e0.y, ve, r.y);
                r.z = fmaf(e1.x, ve, r.z);
                r.w = fmaf(e1.y, ve, r.w);
            }
        }
    }

    float4 bias = __ldg(reinterpret_cast<const float4*>(b) + (ubase >> 2));
    r.x += bias.x; r.y += bias.y; r.z += bias.z; r.w += bias.w;
    *reinterpret_cast<float4*>(out + (size_t)warp * UNITS + ubase) = r;
}

extern "C" void kernel_launch(void* const* d_in, const int* in_sizes, int n_in,
                              void* d_out, int out_size) {
    const float* vals = (const float*)d_in[0];
    const int*   rows = (const int*)d_in[1];
    const int*   cols = (const int*)d_in[2];
    const float* W    = (const float*)d_in[3];
    const float* b    = (const float*)d_in[4];
    float* out = (float*)d_out;

    int nnz = in_sizes[0];
    int num_rows = out_size / UNITS;

    const int T = 256;
    int n4 = WCOLS * UNITS / 4;             // 262144 float4s of W
    int nh = (nnz + 1) / 2;                 // threads for 2-wide scatter
    int work = nh > n4 ? nh : n4;

    zero_kernel<<<(num_rows + T - 1) / T, T>>>(num_rows);
    scatter_convert_kernel<<<(work + T - 1) / T, T>>>(vals, rows, cols, W, nnz, n4);
    int gblocks = (int)(((long)num_rows * 32 + T - 1) / T);
    row_gather_kernel<<<gblocks, T>>>(b, out, num_rows);
}